// round 7
// baseline (speedup 1.0000x reference)
#include <cuda_runtime.h>
#include <cstdint>

// Problem shape: features [B,N,8] f32, geometry [B,N,3] f32, W [C,8,8] f32,
// n_norm scalar (=N), out [B,N,8] f32.
static constexpr int   D        = 8;     // d_in = d_out
static constexpr int   A_TILE   = 128;   // a-points per CTA (one per thread)
static constexpr int   B_CHUNK  = 16;    // b-points staged in smem per CTA
static constexpr int   C_MAX    = 32;    // max radial basis count supported
static constexpr int   BN_MAX   = 2048;  // max B*N supported
static constexpr int   RG       = 8;     // splits summed per stage-1 reduce thread
static constexpr float R_MAX_F  = 3.5f;
static constexpr float EPS_F    = 1e-12f;
// sqrt(log2(e)): fold nat-exp -> exp2 conversion into the distance scale
static constexpr float SQRT_L2E = 1.20112240878644966f;

// Static scratch (no allocation allowed)
__device__ __align__(16) float g_P[BN_MAX * C_MAX * D];                    // 2 MB
__device__ __align__(16) float g_partial[(BN_MAX / B_CHUNK) * BN_MAX * D]; // 8 MB
__device__ __align__(16) float g_p2[(BN_MAX / B_CHUNK / RG) * BN_MAX * D]; // 1 MB

// n_norm may arrive as int32/int64 (python int) or float32.
__device__ __forceinline__ float decode_n(const void* p) {
    int iv = *(const int*)p;
    if (iv > 0 && iv < (1 << 30)) return (float)iv;
    return *(const float*)p;
}

// ---------------------------------------------------------------------------
// Kernel 1: P[zb,c,i] = (1/sqrt(n)) * sum_j W[c,i,j] * f[zb,j]
// Thread per (zb, c, i-half): 131K threads, 10 independent LDG.128, 32 FMAs.
// ---------------------------------------------------------------------------
__global__ void precomp_P(const float* __restrict__ f,
                          const float* __restrict__ W,
                          const void* __restrict__ nptr,
                          int BN, int C) {
    int idx = blockIdx.x * blockDim.x + threadIdx.x;
    if (idx >= BN * C * 2) return;
    const int h  = idx & 1;          // i-half: rows 4h..4h+3
    const int t  = idx >> 1;
    const int c  = t % C;
    const int zb = t / C;
    const float scale = rsqrtf(decode_n(nptr));

    const float4* fr = (const float4*)(f + (size_t)zb * D);
    const float4 f0 = __ldg(fr);
    const float4 f1 = __ldg(fr + 1);
    const float4* wr = (const float4*)(W + ((size_t)c * D + 4 * h) * D);

    float o[4];
#pragma unroll
    for (int i = 0; i < 4; ++i) {
        const float4 w0 = __ldg(wr + 2 * i);
        const float4 w1 = __ldg(wr + 2 * i + 1);
        float s = w0.x * f0.x;
        s = fmaf(w0.y, f0.y, s);
        s = fmaf(w0.z, f0.z, s);
        s = fmaf(w0.w, f0.w, s);
        s = fmaf(w1.x, f1.x, s);
        s = fmaf(w1.y, f1.y, s);
        s = fmaf(w1.z, f1.z, s);
        s = fmaf(w1.w, f1.w, s);
        o[i] = s * scale;
    }
    ((float4*)g_P)[idx] = make_float4(o[0], o[1], o[2], o[3]);
}

// ---------------------------------------------------------------------------
// Kernel 2: partial[split][a][i] = sum_{b in chunk} sum_{c=0..C-1}
//                                   exp(-(t_ab - c)^2) * P[b][c][i]
// c loop is warp-UNIFORM: smem reads broadcast; exp underflows to exact 0
// outside the support so no windowing branch is needed. ts for all 16 b's is
// hoisted so the inner loop is pure FMA/MUFU with no sqrt dependency.
// ---------------------------------------------------------------------------
template <int CT>
__global__ void __launch_bounds__(A_TILE)
conv_main(const float* __restrict__ geo, const void* __restrict__ nptr,
          int BN, int Crt) {
    const int C  = (CT > 0) ? CT : Crt;
    const int N  = (int)decode_n(nptr);
    const int b0 = blockIdx.y * B_CHUNK;        // b offset within z
    if (b0 >= N) return;                        // inactive split
    const int nb  = min(B_CHUNK, N - b0);
    const int ag0 = blockIdx.x * A_TILE;        // global a start (within one z)
    const int z   = ag0 / N;
    const int bg0 = z * N + b0;                 // global b start

    __shared__ float4 Ps[B_CHUNK * C_MAX * 2];  // [bb][c][half] = P[b][c][0..7]
    __shared__ float  sgx[B_CHUNK], sgy[B_CHUNK], sgz[B_CHUNK];

    const int tid = threadIdx.x;
    {
        const float4* gp = (const float4*)(g_P + (size_t)bg0 * C * D);
        const int tot = nb * C * 2;
        for (int k = tid; k < tot; k += A_TILE) Ps[k] = gp[k];
        // zero-fill tail slots so 0*garbage never produces NaN
        for (int k = tot + tid; k < B_CHUNK * C * 2; k += A_TILE)
            Ps[k] = make_float4(0.f, 0.f, 0.f, 0.f);
        if (tid < B_CHUNK) {
            // tail lanes duplicate a valid point; they multiply zeroed Ps rows
            const int bsrc = bg0 + min(tid, nb - 1);
            const float* gb = geo + (size_t)bsrc * 3;
            sgx[tid] = gb[0]; sgy[tid] = gb[1]; sgz[tid] = gb[2];
        }
    }
    __syncthreads();

    const int a = ag0 + tid;
    const float* ga = geo + (size_t)a * 3;
    const float gax = __ldg(ga), gay = __ldg(ga + 1), gaz = __ldg(ga + 2);
    const float kscale = ((float)(C - 1) / R_MAX_F) * SQRT_L2E;

    // Hoist ts for all b's: independent MUFU sqrt chains, full MLP.
    float tsv[B_CHUNK];
#pragma unroll
    for (int bb = 0; bb < B_CHUNK; ++bb) {
        const float dx = sgx[bb] - gax;
        const float dy = sgy[bb] - gay;
        const float dz = sgz[bb] - gaz;
        const float d2 = fmaf(dx, dx, fmaf(dy, dy, fmaf(dz, dz, EPS_F)));
        float dd;
        asm("sqrt.approx.f32 %0, %1;" : "=f"(dd) : "f"(d2));
        tsv[bb] = dd * kscale;                  // = t * sqrt(log2e)
    }

    unsigned long long acc0 = 0ull, acc1 = 0ull, acc2 = 0ull, acc3 = 0ull;

    // bb rolled (keeps code ~5KB, inside L0 I$); c fully unrolled.
    for (int bb = 0; bb < B_CHUNK; ++bb) {
        const float ts = tsv[bb];
        const ulonglong2* pb = (const ulonglong2*)(Ps + (size_t)bb * (C * 2));
#pragma unroll
        for (int c = 0; c < C; ++c) {
            const float v   = ts - (float)c * SQRT_L2E;  // const folds
            const float arg = -v * v;
            float e;
            asm("ex2.approx.f32 %0, %1;" : "=f"(e) : "f"(arg)); // exp(-u^2)
            unsigned long long ee;
            asm("mov.b64 %0, {%1, %1};" : "=l"(ee) : "f"(e));
            const ulonglong2 q0 = pb[2 * c];     // P[b][c][0..3]
            const ulonglong2 q1 = pb[2 * c + 1]; // P[b][c][4..7]
            asm("fma.rn.f32x2 %0, %1, %2, %0;" : "+l"(acc0) : "l"(q0.x), "l"(ee));
            asm("fma.rn.f32x2 %0, %1, %2, %0;" : "+l"(acc1) : "l"(q0.y), "l"(ee));
            asm("fma.rn.f32x2 %0, %1, %2, %0;" : "+l"(acc2) : "l"(q1.x), "l"(ee));
            asm("fma.rn.f32x2 %0, %1, %2, %0;" : "+l"(acc3) : "l"(q1.y), "l"(ee));
        }
    }

    const float2 r0 = *(const float2*)&acc0;
    const float2 r1 = *(const float2*)&acc1;
    const float2 r2 = *(const float2*)&acc2;
    const float2 r3 = *(const float2*)&acc3;
    float4* op = (float4*)(g_partial + ((size_t)blockIdx.y * BN + a) * D);
    op[0] = make_float4(r0.x, r0.y, r1.x, r1.y);
    op[1] = make_float4(r2.x, r2.y, r3.x, r3.y);
}

// ---------------------------------------------------------------------------
// Kernel 3a: stage-1 reduce — thread (g, idx) sums splits [g*RG, g*RG+RG)
// ---------------------------------------------------------------------------
__global__ void reduce_s1(const void* __restrict__ nptr, int BN, int Gmax) {
    int tid = blockIdx.x * blockDim.x + threadIdx.x;
    const int BND = BN * D;
    if (tid >= BND * Gmax) return;
    const int g   = tid / BND;
    const int idx = tid - g * BND;
    const int N = (int)decode_n(nptr);
    const int S = (N + B_CHUNK - 1) / B_CHUNK;   // active splits
    float s = 0.f;
#pragma unroll
    for (int j = 0; j < RG; ++j) {
        const int k = g * RG + j;
        if (k < S) s += g_partial[(size_t)k * BND + idx];
    }
    g_p2[(size_t)g * BND + idx] = s;   // inactive groups write 0
}

// ---------------------------------------------------------------------------
// Kernel 3b: stage-2 reduce — sum all Gmax group rows (inactive rows are 0)
// ---------------------------------------------------------------------------
__global__ void reduce_s2(int BN, int Gmax, float* __restrict__ out) {
    int idx = blockIdx.x * blockDim.x + threadIdx.x;
    const int BND = BN * D;
    if (idx >= BND) return;
    float s = 0.f;
    for (int g = 0; g < Gmax; ++g) s += g_p2[(size_t)g * BND + idx];
    out[idx] = s;
}

// ---------------------------------------------------------------------------
extern "C" void kernel_launch(void* const* d_in, const int* in_sizes, int n_in,
                              void* d_out, int out_size) {
    const float* f   = (const float*)d_in[0];   // features [B,N,8]
    const float* geo = (const float*)d_in[1];   // geometry [B,N,3]
    const float* W   = (const float*)d_in[2];   // W [C,8,8]
    const void*  nn  = d_in[3];                 // n_norm scalar
    float* out = (float*)d_out;

    const int BN = in_sizes[1] / 3;             // B*N
    const int C  = in_sizes[2] / (D * D);       // radial basis count
    const int Smax = BN / B_CHUNK;              // over-provisioned split count
    const int Gmax = (Smax + RG - 1) / RG;      // stage-1 group count

    // 1) P precompute: thread per (zb, c, half)
    {
        int threads = BN * C * 2;
        precomp_P<<<(threads + 255) / 256, 256>>>(f, W, nn, BN, C);
    }
    // 2) Main contraction (grid.y over-provisioned; inactive splits exit)
    {
        dim3 grid(BN / A_TILE, Smax);
        if (C == 32)
            conv_main<32><<<grid, A_TILE>>>(geo, nn, BN, C);
        else
            conv_main<0><<<grid, A_TILE>>>(geo, nn, BN, C);
    }
    // 3) Two-stage deterministic reduce
    {
        int t1 = BN * D * Gmax;
        reduce_s1<<<(t1 + 255) / 256, 256>>>(nn, BN, Gmax);
        int t2 = BN * D;
        reduce_s2<<<(t2 + 255) / 256, 256>>>(BN, Gmax, out);
    }
}